// round 14
// baseline (speedup 1.0000x reference)
#include <cuda_runtime.h>
#include <cuda_fp16.h>
#include <cstdint>
#include <cmath>

#define NTOK 8192
#define HDIM 2048
#define IDIM 8192
#define KSEL 2048
#define DELTA 1.5e-3f
#define BCAP 160
#define GSTR (2 * IDIM)          // fused gate|v row stride

__device__ float g_gv [(size_t)NTOK * GSTR];        // [N, 2I]: gate | v
__device__ __half g_xh [(size_t)NTOK * HDIM];       // x  h-plane
__device__ __half g_w1 [2 * (size_t)IDIM * HDIM];   // [Wg_h ; Wu_h]
__device__ __half g_wd [(size_t)HDIM * IDIM];       // Wd h-plane
__device__ __half g_ah [(size_t)NTOK * IDIM];       // activation h-plane

__device__ __forceinline__ uint32_t smem_u32(const void* p) {
    uint32_t a;
    asm("{ .reg .u64 t; cvta.to.shared.u64 t, %1; cvt.u32.u64 %0, t; }" : "=r"(a) : "l"(p));
    return a;
}
#define CP16(d, s)  asm volatile("cp.async.cg.shared.global [%0], [%1], 16;" :: "r"(d), "l"(s) : "memory")
#define CP_COMMIT() asm volatile("cp.async.commit_group;" ::: "memory")
#define CP_WAIT(n)  asm volatile("cp.async.wait_group %0;" :: "n"(n) : "memory")
#define LDM4(r0, r1, r2, r3, a) \
    asm volatile("ldmatrix.sync.aligned.m8n8.x4.shared.b16 {%0,%1,%2,%3}, [%4];" \
                 : "=r"(r0), "=r"(r1), "=r"(r2), "=r"(r3) : "r"(a))
#define MMA16816(c0, c1, c2, c3, a0, a1, a2, a3, b0, b1) \
    asm volatile("mma.sync.aligned.m16n8k16.row.col.f32.f16.f16.f32 " \
                 "{%0,%1,%2,%3},{%4,%5,%6,%7},{%8,%9},{%0,%1,%2,%3};" \
                 : "+f"(c0), "+f"(c1), "+f"(c2), "+f"(c3) \
                 : "r"(a0), "r"(a1), "r"(a2), "r"(a3), "r"(b0), "r"(b1))
#define SWZ(o) ((uint32_t)(o) ^ ((((uint32_t)(o)) >> 3) & 0x70u))

__device__ __forceinline__ unsigned f2k(float f) {
    unsigned b = __float_as_uint(f);
    return (b & 0x80000000u) ? ~b : (b | 0x80000000u);
}
__device__ __forceinline__ float k2f(unsigned u) {
    unsigned b = (u & 0x80000000u) ? (u & 0x7FFFFFFFu) : ~u;
    return __uint_as_float(b);
}

// ---------------------------------------------------------------------------
// Plain fp16 GEMM: C[m][n] = A[m,:] . B[n,:]   (A [M,K], B [N,K], C [M,N])
// CTA 128x256, 256 thr, warp tile 64x64, K-chunk 64, 4-stage cp.async.
// ---------------------------------------------------------------------------
#define BM 128
#define BN 256
#define STAGE 49152              // A 16KB + B 32KB
#define NSTG 4
#define SMEMSZ (NSTG * STAGE)

__device__ __forceinline__ void hload(uint32_t st,
    const __half* __restrict__ A, const __half* __restrict__ B,
    int bm, int bn, int K, int k0, int tid)
{
#pragma unroll
    for (int i = 0; i < 4; i++) {
        int idx = tid + i * 256;
        int r = idx >> 3, c8 = idx & 7;
        CP16(st + SWZ(r * 128 + c8 * 16), A + (size_t)(bm + r) * K + k0 + c8 * 8);
    }
#pragma unroll
    for (int i = 0; i < 8; i++) {
        int idx = tid + i * 256;
        int r = idx >> 3, c8 = idx & 7;
        CP16(st + 16384u + SWZ(r * 128 + c8 * 16), B + (size_t)(bn + r) * K + k0 + c8 * 8);
    }
    CP_COMMIT();
}

__global__ __launch_bounds__(256, 1)
void hgemm(const __half* __restrict__ A, const __half* __restrict__ B,
           float* __restrict__ C, int N, int K)
{
    extern __shared__ char smem[];
    const uint32_t sb = smem_u32(smem);
    const int tid = threadIdx.x, wid = tid >> 5, lane = tid & 31;
    const int bm = blockIdx.y * BM, bn = blockIdx.x * BN;
    const int wm = (wid >> 2) * 64, wn = (wid & 3) * 64;
    const int CH = K >> 6;

    float c[4][8][4];
#pragma unroll
    for (int i = 0; i < 4; i++)
#pragma unroll
        for (int j = 0; j < 8; j++)
#pragma unroll
            for (int q = 0; q < 4; q++) c[i][j][q] = 0.f;

#pragma unroll
    for (int s = 0; s < NSTG - 1; s++)
        hload(sb + (uint32_t)s * STAGE, A, B, bm, bn, K, s * 64, tid);

    const int a_mrow = lane & 15;
    const int a_kc   = lane >> 4;
    const int b_nrow = (lane & 7) + ((lane >> 4) << 3);
    const int b_kc   = (lane >> 3) & 1;

    for (int t = 0; t < CH; t++) {
        const uint32_t st = sb + (uint32_t)(t % NSTG) * STAGE;
        CP_WAIT(NSTG - 2);
        __syncthreads();
        if (t + NSTG - 1 < CH)
            hload(sb + (uint32_t)((t + NSTG - 1) % NSTG) * STAGE, A, B, bm, bn, K,
                  (t + NSTG - 1) * 64, tid);
        else
            CP_COMMIT();

#pragma unroll
        for (int kk = 0; kk < 4; kk++) {
            uint32_t a[4][4], b[4][4];
#pragma unroll
            for (int mt = 0; mt < 4; mt++) {
                int r = wm + mt * 16 + a_mrow;
                int ch = kk * 2 + a_kc;
                LDM4(a[mt][0], a[mt][1], a[mt][2], a[mt][3],
                     st + SWZ(r * 128 + ch * 16));
            }
#pragma unroll
            for (int nt = 0; nt < 4; nt++) {
                int r = wn + nt * 16 + b_nrow;
                int ch = kk * 2 + b_kc;
                LDM4(b[nt][0], b[nt][1], b[nt][2], b[nt][3],
                     st + 16384u + SWZ(r * 128 + ch * 16));
            }
#pragma unroll
            for (int mt = 0; mt < 4; mt++)
#pragma unroll
                for (int j = 0; j < 8; j++)
                    MMA16816(c[mt][j][0], c[mt][j][1], c[mt][j][2], c[mt][j][3],
                             a[mt][0], a[mt][1], a[mt][2], a[mt][3],
                             b[j >> 1][(j & 1) * 2], b[j >> 1][(j & 1) * 2 + 1]);
        }
    }

#pragma unroll
    for (int mt = 0; mt < 4; mt++) {
        int row = bm + wm + mt * 16 + (lane >> 2);
#pragma unroll
        for (int j = 0; j < 8; j++) {
            int col = bn + wn + j * 8 + (lane & 3) * 2;
            *(float2*)(C + (size_t)row * N + col)       = make_float2(c[mt][j][0], c[mt][j][1]);
            *(float2*)(C + (size_t)(row + 8) * N + col) = make_float2(c[mt][j][2], c[mt][j][3]);
        }
    }
}

// ---------------------------------------------------------------------------
__global__ void split1h(const float4* __restrict__ a, __half* __restrict__ o, size_t n)
{
    const size_t n4 = n >> 2;
    size_t i = (size_t)blockIdx.x * blockDim.x + threadIdx.x;
    for (; i < n4; i += (size_t)gridDim.x * blockDim.x) {
        float4 x = a[i];
        *(__half2*)(o + 4 * i)     = __halves2half2(__float2half_rn(x.x), __float2half_rn(x.y));
        *(__half2*)(o + 4 * i + 2) = __halves2half2(__float2half_rn(x.z), __float2half_rn(x.w));
    }
}

// ---------------------------------------------------------------------------
// Top-K with exact boundary resolution (staged cooperative recompute of band
// gates in the reference's sequential-k fp32 order).
// Reads fused [gate|v] rows (stride GSTR); writes fp16 activation h-plane.
// ---------------------------------------------------------------------------
#define GRP 8
#define CHK 256

__global__ __launch_bounds__(256)
void topk_kernel(const float* __restrict__ gv,
                 const float* __restrict__ x, const float* __restrict__ Wg,
                 __half* __restrict__ ah)
{
    __shared__ unsigned s_u[IDIM];
    __shared__ float    s_buf[GRP][CHK + 4];
    __shared__ float    s_xc[CHK];
    __shared__ int      hist[256];
    __shared__ int      s_bidx[BCAP];
    __shared__ float    s_bg[BCAP];
    __shared__ unsigned char s_bsel[BCAP];
    __shared__ unsigned s_prefix;
    __shared__ int s_kk, s_na, s_nb;

    const int row = blockIdx.x, tid = threadIdx.x;
    const float* grow = gv + (size_t)row * GSTR;
    const float* vrow = grow + IDIM;
    const float* xrow = x + (size_t)row * HDIM;

    for (int i = tid * 4; i < IDIM; i += 1024) {
        float4 g4 = *(const float4*)(grow + i);
        s_u[i]     = f2k(g4.x); s_u[i + 1] = f2k(g4.y);
        s_u[i + 2] = f2k(g4.z); s_u[i + 3] = f2k(g4.w);
    }
    if (tid == 0) { s_prefix = 0u; s_kk = KSEL; s_na = 0; s_nb = 0; }
    __syncthreads();

#pragma unroll
    for (int pass = 0; pass < 4; pass++) {
        const int shift = 24 - 8 * pass;
        hist[tid] = 0;
        __syncthreads();
        const unsigned prefix = s_prefix;
        const unsigned himask = (pass == 0) ? 0u : (0xFFFFFFFFu << (shift + 8));
        for (int i = tid; i < IDIM; i += 256) {
            unsigned u = s_u[i];
            if ((u & himask) == prefix) atomicAdd(&hist[(u >> shift) & 255], 1);
        }
        __syncthreads();
        if (tid == 0) {
            int kk = s_kk, cum = 0, b = 0;
            for (int q = 255; q >= 0; q--) { cum += hist[q]; if (cum >= kk) { b = q; break; } }
            s_kk = kk - (cum - hist[b]);
            s_prefix = prefix | ((unsigned)b << shift);
        }
        __syncthreads();
    }
    const unsigned t = s_prefix;
    const float gt = k2f(t);
    const unsigned hik = f2k(gt + DELTA);
    const unsigned lok = f2k(gt - DELTA);
    __syncthreads();

    for (int i = tid; i < IDIM; i += 256) {
        unsigned u = s_u[i];
        if (u > hik) atomicAdd(&s_na, 1);
        else if (u >= lok) {
            int p = atomicAdd(&s_nb, 1);
            if (p < BCAP) s_bidx[p] = i;
        }
    }
    __syncthreads();
    const int nb = s_nb;
    const int nb_c = nb < BCAP ? nb : BCAP;
    const bool ovf = nb > BCAP;
    const int quota = KSEL - s_na;

    if (!ovf) {
        for (int g0 = 0; g0 < nb_c; g0 += GRP) {
            const int ng = min(GRP, nb_c - g0);
            float accR = 0.f;
            for (int c0 = 0; c0 < HDIM; c0 += CHK) {
                if (tid < CHK / 4)
                    *(float4*)(s_xc + tid * 4) = *(const float4*)(xrow + c0 + tid * 4);
#pragma unroll
                for (int q = 0; q < (GRP * CHK / 4) / 256; q++) {
                    int idx = tid + q * 256;
                    int e = idx / (CHK / 4);
                    int f = idx % (CHK / 4);
                    if (e < ng)
                        *(float4*)(&s_buf[e][f * 4]) =
                            *(const float4*)(Wg + (size_t)s_bidx[g0 + e] * HDIM + c0 + f * 4);
                }
                __syncthreads();
                if (tid < ng) {
                    const float* bw = s_buf[tid];
#pragma unroll 8
                    for (int kk = 0; kk < CHK; kk++)
                        accR = fmaf(s_xc[kk], bw[kk], accR);
                }
                __syncthreads();
            }
            if (tid < ng) s_bg[g0 + tid] = accR;
        }
        __syncthreads();
        if (tid < nb_c) {
            const float gi = s_bg[tid];
            const int ii = s_bidx[tid];
            int r = 0;
            for (int j = 0; j < nb_c; j++) {
                float gj = s_bg[j];
                if (gj > gi || (gj == gi && s_bidx[j] < ii)) r++;
            }
            s_bsel[tid] = (r < quota) ? 1 : 0;
        }
        __syncthreads();
    }

    for (int i = tid * 4; i < IDIM; i += 1024) {
        float4 v4 = *(const float4*)(vrow + i);
        __half hs[4];
#pragma unroll
        for (int q = 0; q < 4; q++) {
            const unsigned u = s_u[i + q];
            float o = 0.f;
            if (u > hik) {
                float g = k2f(u);
                o = (g / (1.f + expf(-g))) * ((const float*)&v4)[q];
            } else if (u >= lok) {
                if (!ovf) {
                    for (int j = 0; j < nb_c; j++)
                        if (s_bidx[j] == i + q) {
                            if (s_bsel[j]) {
                                float g = s_bg[j];
                                o = (g / (1.f + expf(-g))) * ((const float*)&v4)[q];
                            }
                            break;
                        }
                } else if (u >= t) {
                    float g = k2f(u);
                    o = (g / (1.f + expf(-g))) * ((const float*)&v4)[q];
                }
            }
            hs[q] = __float2half_rn(o);
        }
        const size_t idx = (size_t)row * IDIM + i;
        *(__half2*)(ah + idx)     = __halves2half2(hs[0], hs[1]);
        *(__half2*)(ah + idx + 2) = __halves2half2(hs[2], hs[3]);
    }
}

// ---------------------------------------------------------------------------
extern "C" void kernel_launch(void* const* d_in, const int* in_sizes, int n_in,
                              void* d_out, int out_size)
{
    const float* x  = (const float*)d_in[0];
    const float* Wg = (const float*)d_in[1];
    const float* Wu = (const float*)d_in[2];
    const float* Wd = (const float*)d_in[3];
    float* out = (float*)d_out;

    float* gv;
    __half *xh, *w1, *wd, *ah;
    cudaGetSymbolAddress((void**)&gv, g_gv);
    cudaGetSymbolAddress((void**)&xh, g_xh);
    cudaGetSymbolAddress((void**)&w1, g_w1);
    cudaGetSymbolAddress((void**)&wd, g_wd);
    cudaGetSymbolAddress((void**)&ah, g_ah);

    const size_t nx = (size_t)NTOK * HDIM;
    const size_t nw = (size_t)IDIM * HDIM;

    cudaFuncSetAttribute(hgemm, cudaFuncAttributeMaxDynamicSharedMemorySize, SMEMSZ);

    split1h<<<2048, 256>>>((const float4*)x,  xh, nx);
    split1h<<<2048, 256>>>((const float4*)Wg, w1, nw);
    split1h<<<2048, 256>>>((const float4*)Wu, w1 + nw, nw);
    split1h<<<2048, 256>>>((const float4*)Wd, wd, nw);

    // Fused [gate|v] = x @ [Wg;Wu]^T : M=8192, N=16384, K=2048
    hgemm<<<dim3(GSTR / BN, NTOK / BM), 256, SMEMSZ>>>(xh, w1, gv, GSTR, HDIM);
    // exact-boundary top-k + silu*v -> fp16 activation
    topk_kernel<<<NTOK, 256>>>(gv, x, Wg, ah);
    // out = act @ Wd^T : M=8192, N=2048, K=8192
    hgemm<<<dim3(HDIM / BN, NTOK / BM), 256, SMEMSZ>>>(ah, wd, out, HDIM, IDIM);
}

// round 15
// speedup vs baseline: 1.7714x; 1.7714x over previous
#include <cuda_runtime.h>
#include <cuda_fp16.h>
#include <cstdint>
#include <cmath>

#define NTOK 8192
#define HDIM 2048
#define IDIM 8192
#define KSEL 2048
#define DELTA 1.5e-3f
#define BCAP 160
#define GSTR (2 * IDIM)          // fused gate|v row stride

__device__ float g_gv [(size_t)NTOK * GSTR];        // [N, 2I]: gate | v
__device__ __half g_xh [(size_t)NTOK * HDIM];       // x  h-plane
__device__ __half g_w1 [2 * (size_t)IDIM * HDIM];   // [Wg_h ; Wu_h]
__device__ __half g_wd [(size_t)HDIM * IDIM];       // Wd h-plane
__device__ __half g_ah [(size_t)NTOK * IDIM];       // activation h-plane

__device__ __forceinline__ uint32_t smem_u32(const void* p) {
    uint32_t a;
    asm("{ .reg .u64 t; cvta.to.shared.u64 t, %1; cvt.u32.u64 %0, t; }" : "=r"(a) : "l"(p));
    return a;
}
#define CP16(d, s)  asm volatile("cp.async.cg.shared.global [%0], [%1], 16;" :: "r"(d), "l"(s) : "memory")
#define CP_COMMIT() asm volatile("cp.async.commit_group;" ::: "memory")
#define CP_WAIT(n)  asm volatile("cp.async.wait_group %0;" :: "n"(n) : "memory")
#define LDM4(r0, r1, r2, r3, a) \
    asm volatile("ldmatrix.sync.aligned.m8n8.x4.shared.b16 {%0,%1,%2,%3}, [%4];" \
                 : "=r"(r0), "=r"(r1), "=r"(r2), "=r"(r3) : "r"(a))
#define MMA16816(c0, c1, c2, c3, a0, a1, a2, a3, b0, b1) \
    asm volatile("mma.sync.aligned.m16n8k16.row.col.f32.f16.f16.f32 " \
                 "{%0,%1,%2,%3},{%4,%5,%6,%7},{%8,%9},{%0,%1,%2,%3};" \
                 : "+f"(c0), "+f"(c1), "+f"(c2), "+f"(c3) \
                 : "r"(a0), "r"(a1), "r"(a2), "r"(a3), "r"(b0), "r"(b1))
#define SWZ(o) ((uint32_t)(o) ^ ((((uint32_t)(o)) >> 3) & 0x70u))

__device__ __forceinline__ unsigned f2k(float f) {
    unsigned b = __float_as_uint(f);
    return (b & 0x80000000u) ? ~b : (b | 0x80000000u);
}
__device__ __forceinline__ float k2f(unsigned u) {
    unsigned b = (u & 0x80000000u) ? (u & 0x7FFFFFFFu) : ~u;
    return __uint_as_float(b);
}

// ---------------------------------------------------------------------------
// Plain fp16 GEMM: C[m][n] = A[m,:] . B[n,:]   (A [M,K], B [N,K], C [M,N])
// CTA 128x256, 256 thr, warp tile 64x64.
// K-chunk 128 = two 64-col sub-tiles (SW128 layout per sub), 2-stage cp.async.
// Stage layout: [A sub0 16KB][A sub1 16KB][B sub0 32KB][B sub1 32KB] = 96KB.
// ---------------------------------------------------------------------------
#define BM 128
#define BN 256
#define STAGE 98304
#define NSTG 2
#define SMEMSZ (NSTG * STAGE)

__device__ __forceinline__ void hload(uint32_t st,
    const __half* __restrict__ A, const __half* __restrict__ B,
    int bm, int bn, int K, int k0, int tid)
{
#pragma unroll
    for (int i = 0; i < 8; i++) {            // A: 2 subs x 1024 16B chunks
        int idx = tid + i * 256;
        int sub = idx >> 10;
        int r = (idx >> 3) & 127, c8 = idx & 7;
        CP16(st + (uint32_t)sub * 16384u + SWZ(r * 128 + c8 * 16),
             A + (size_t)(bm + r) * K + k0 + sub * 64 + c8 * 8);
    }
#pragma unroll
    for (int i = 0; i < 16; i++) {           // B: 2 subs x 2048 16B chunks
        int idx = tid + i * 256;
        int sub = idx >> 11;
        int r = (idx >> 3) & 255, c8 = idx & 7;
        CP16(st + 32768u + (uint32_t)sub * 32768u + SWZ(r * 128 + c8 * 16),
             B + (size_t)(bn + r) * K + k0 + sub * 64 + c8 * 8);
    }
    CP_COMMIT();
}

__global__ __launch_bounds__(256, 1)
void hgemm(const __half* __restrict__ A, const __half* __restrict__ B,
           float* __restrict__ C, int N, int K)
{
    extern __shared__ char smem[];
    const uint32_t sb = smem_u32(smem);
    const int tid = threadIdx.x, wid = tid >> 5, lane = tid & 31;
    const int bm = blockIdx.y * BM, bn = blockIdx.x * BN;
    const int wm = (wid >> 2) * 64, wn = (wid & 3) * 64;
    const int CH = K >> 7;                   // 128-wide chunks

    float c[4][8][4];
#pragma unroll
    for (int i = 0; i < 4; i++)
#pragma unroll
        for (int j = 0; j < 8; j++)
#pragma unroll
            for (int q = 0; q < 4; q++) c[i][j][q] = 0.f;

    hload(sb, A, B, bm, bn, K, 0, tid);      // prologue: stage 0

    const int a_mrow = lane & 15;
    const int a_kc   = lane >> 4;
    const int b_nrow = (lane & 7) + ((lane >> 4) << 3);
    const int b_kc   = (lane >> 3) & 1;

    for (int t = 0; t < CH; t++) {
        const uint32_t st = sb + (uint32_t)(t & 1) * STAGE;
        CP_WAIT(0);                          // stage t's load complete
        __syncthreads();
        if (t + 1 < CH)
            hload(sb + (uint32_t)((t + 1) & 1) * STAGE, A, B, bm, bn, K,
                  (t + 1) * 128, tid);
        else
            CP_COMMIT();

#pragma unroll
        for (int kk = 0; kk < 8; kk++) {
            const uint32_t asub = st + (uint32_t)(kk >> 2) * 16384u;
            const uint32_t bsub = st + 32768u + (uint32_t)(kk >> 2) * 32768u;
            const int kx = kk & 3;
            uint32_t a[4][4], b[4][4];
#pragma unroll
            for (int mt = 0; mt < 4; mt++) {
                int r = wm + mt * 16 + a_mrow;
                int ch = kx * 2 + a_kc;
                LDM4(a[mt][0], a[mt][1], a[mt][2], a[mt][3],
                     asub + SWZ(r * 128 + ch * 16));
            }
#pragma unroll
            for (int nt = 0; nt < 4; nt++) {
                int r = wn + nt * 16 + b_nrow;
                int ch = kx * 2 + b_kc;
                LDM4(b[nt][0], b[nt][1], b[nt][2], b[nt][3],
                     bsub + SWZ(r * 128 + ch * 16));
            }
#pragma unroll
            for (int mt = 0; mt < 4; mt++)
#pragma unroll
                for (int j = 0; j < 8; j++)
                    MMA16816(c[mt][j][0], c[mt][j][1], c[mt][j][2], c[mt][j][3],
                             a[mt][0], a[mt][1], a[mt][2], a[mt][3],
                             b[j >> 1][(j & 1) * 2], b[j >> 1][(j & 1) * 2 + 1]);
        }
    }

#pragma unroll
    for (int mt = 0; mt < 4; mt++) {
        int row = bm + wm + mt * 16 + (lane >> 2);
#pragma unroll
        for (int j = 0; j < 8; j++) {
            int col = bn + wn + j * 8 + (lane & 3) * 2;
            *(float2*)(C + (size_t)row * N + col)       = make_float2(c[mt][j][0], c[mt][j][1]);
            *(float2*)(C + (size_t)(row + 8) * N + col) = make_float2(c[mt][j][2], c[mt][j][3]);
        }
    }
}

// ---------------------------------------------------------------------------
__global__ void split1h(const float4* __restrict__ a, __half* __restrict__ o, size_t n)
{
    const size_t n4 = n >> 2;
    size_t i = (size_t)blockIdx.x * blockDim.x + threadIdx.x;
    for (; i < n4; i += (size_t)gridDim.x * blockDim.x) {
        float4 x = a[i];
        *(__half2*)(o + 4 * i)     = __halves2half2(__float2half_rn(x.x), __float2half_rn(x.y));
        *(__half2*)(o + 4 * i + 2) = __halves2half2(__float2half_rn(x.z), __float2half_rn(x.w));
    }
}

// ---------------------------------------------------------------------------
// Top-K with exact boundary resolution (staged cooperative recompute of band
// gates in the reference's sequential-k fp32 order).
// ---------------------------------------------------------------------------
#define GRP 8
#define CHK 256

__global__ __launch_bounds__(256)
void topk_kernel(const float* __restrict__ gv,
                 const float* __restrict__ x, const float* __restrict__ Wg,
                 __half* __restrict__ ah)
{
    __shared__ unsigned s_u[IDIM];
    __shared__ float    s_buf[GRP][CHK + 4];
    __shared__ float    s_xc[CHK];
    __shared__ int      hist[256];
    __shared__ int      s_bidx[BCAP];
    __shared__ float    s_bg[BCAP];
    __shared__ unsigned char s_bsel[BCAP];
    __shared__ unsigned s_prefix;
    __shared__ int s_kk, s_na, s_nb;

    const int row = blockIdx.x, tid = threadIdx.x;
    const float* grow = gv + (size_t)row * GSTR;
    const float* vrow = grow + IDIM;
    const float* xrow = x + (size_t)row * HDIM;

    for (int i = tid * 4; i < IDIM; i += 1024) {
        float4 g4 = *(const float4*)(grow + i);
        s_u[i]     = f2k(g4.x); s_u[i + 1] = f2k(g4.y);
        s_u[i + 2] = f2k(g4.z); s_u[i + 3] = f2k(g4.w);
    }
    if (tid == 0) { s_prefix = 0u; s_kk = KSEL; s_na = 0; s_nb = 0; }
    __syncthreads();

#pragma unroll
    for (int pass = 0; pass < 4; pass++) {
        const int shift = 24 - 8 * pass;
        hist[tid] = 0;
        __syncthreads();
        const unsigned prefix = s_prefix;
        const unsigned himask = (pass == 0) ? 0u : (0xFFFFFFFFu << (shift + 8));
        for (int i = tid; i < IDIM; i += 256) {
            unsigned u = s_u[i];
            if ((u & himask) == prefix) atomicAdd(&hist[(u >> shift) & 255], 1);
        }
        __syncthreads();
        if (tid == 0) {
            int kk = s_kk, cum = 0, b = 0;
            for (int q = 255; q >= 0; q--) { cum += hist[q]; if (cum >= kk) { b = q; break; } }
            s_kk = kk - (cum - hist[b]);
            s_prefix = prefix | ((unsigned)b << shift);
        }
        __syncthreads();
    }
    const unsigned t = s_prefix;
    const float gt = k2f(t);
    const unsigned hik = f2k(gt + DELTA);
    const unsigned lok = f2k(gt - DELTA);
    __syncthreads();

    for (int i = tid; i < IDIM; i += 256) {
        unsigned u = s_u[i];
        if (u > hik) atomicAdd(&s_na, 1);
        else if (u >= lok) {
            int p = atomicAdd(&s_nb, 1);
            if (p < BCAP) s_bidx[p] = i;
        }
    }
    __syncthreads();
    const int nb = s_nb;
    const int nb_c = nb < BCAP ? nb : BCAP;
    const bool ovf = nb > BCAP;
    const int quota = KSEL - s_na;

    if (!ovf) {
        for (int g0 = 0; g0 < nb_c; g0 += GRP) {
            const int ng = min(GRP, nb_c - g0);
            float accR = 0.f;
            for (int c0 = 0; c0 < HDIM; c0 += CHK) {
                if (tid < CHK / 4)
                    *(float4*)(s_xc + tid * 4) = *(const float4*)(xrow + c0 + tid * 4);
#pragma unroll
                for (int q = 0; q < (GRP * CHK / 4) / 256; q++) {
                    int idx = tid + q * 256;
                    int e = idx / (CHK / 4);
                    int f = idx % (CHK / 4);
                    if (e < ng)
                        *(float4*)(&s_buf[e][f * 4]) =
                            *(const float4*)(Wg + (size_t)s_bidx[g0 + e] * HDIM + c0 + f * 4);
                }
                __syncthreads();
                if (tid < ng) {
                    const float* bw = s_buf[tid];
#pragma unroll 8
                    for (int kk = 0; kk < CHK; kk++)
                        accR = fmaf(s_xc[kk], bw[kk], accR);
                }
                __syncthreads();
            }
            if (tid < ng) s_bg[g0 + tid] = accR;
        }
        __syncthreads();
        if (tid < nb_c) {
            const float gi = s_bg[tid];
            const int ii = s_bidx[tid];
            int r = 0;
            for (int j = 0; j < nb_c; j++) {
                float gj = s_bg[j];
                if (gj > gi || (gj == gi && s_bidx[j] < ii)) r++;
            }
            s_bsel[tid] = (r < quota) ? 1 : 0;
        }
        __syncthreads();
    }

    for (int i = tid * 4; i < IDIM; i += 1024) {
        float4 v4 = *(const float4*)(vrow + i);
        __half hs[4];
#pragma unroll
        for (int q = 0; q < 4; q++) {
            const unsigned u = s_u[i + q];
            float o = 0.f;
            if (u > hik) {
                float g = k2f(u);
                o = (g / (1.f + expf(-g))) * ((const float*)&v4)[q];
            } else if (u >= lok) {
                if (!ovf) {
                    for (int j = 0; j < nb_c; j++)
                        if (s_bidx[j] == i + q) {
                            if (s_bsel[j]) {
                                float g = s_bg[j];
                                o = (g / (1.f + expf(-g))) * ((const float*)&v4)[q];
                            }
                            break;
                        }
                } else if (u >= t) {
                    float g = k2f(u);
                    o = (g / (1.f + expf(-g))) * ((const float*)&v4)[q];
                }
            }
            hs[q] = __float2half_rn(o);
        }
        const size_t idx = (size_t)row * IDIM + i;
        *(__half2*)(ah + idx)     = __halves2half2(hs[0], hs[1]);
        *(__half2*)(ah + idx + 2) = __halves2half2(hs[2], hs[3]);
    }
}

// ---------------------------------------------------------------------------
extern "C" void kernel_launch(void* const* d_in, const int* in_sizes, int n_in,
                              void* d_out, int out_size)
{
    const float* x  = (const float*)d_in[0];
    const float* Wg = (const float*)d_in[1];
    const float* Wu = (const float*)d_in[2];
    const float* Wd = (const float*)d_in[3];
    float* out = (float*)d_out;

    float* gv;
    __half *xh, *w1, *wd, *ah;
    cudaGetSymbolAddress((void**)&gv, g_gv);
    cudaGetSymbolAddress((void**)&xh, g_xh);
    cudaGetSymbolAddress((void**)&w1, g_w1);
    cudaGetSymbolAddress((void**)&wd, g_wd);
    cudaGetSymbolAddress((void**)&ah, g_ah);

    const size_t nx = (size_t)NTOK * HDIM;
    const size_t nw = (size_t)IDIM * HDIM;

    cudaFuncSetAttribute(hgemm, cudaFuncAttributeMaxDynamicSharedMemorySize, SMEMSZ);

    split1h<<<2048, 256>>>((const float4*)x,  xh, nx);
    split1h<<<2048, 256>>>((const float4*)Wg, w1, nw);
    split1h<<<2048, 256>>>((const float4*)Wu, w1 + nw, nw);
    split1h<<<2048, 256>>>((const float4*)Wd, wd, nw);

    // Fused [gate|v] = x @ [Wg;Wu]^T : M=8192, N=16384, K=2048
    hgemm<<<dim3(GSTR / BN, NTOK / BM), 256, SMEMSZ>>>(xh, w1, gv, GSTR, HDIM);
    // exact-boundary top-k + silu*v -> fp16 activation
    topk_kernel<<<NTOK, 256>>>(gv, x, Wg, ah);
    // out = act @ Wd^T : M=8192, N=2048, K=8192
    hgemm<<<dim3(HDIM / BN, NTOK / BM), 256, SMEMSZ>>>(ah, wd, out, HDIM, IDIM);
}